// round 10
// baseline (speedup 1.0000x reference)
#include <cuda_runtime.h>
#include <cstdint>

#define K_VOL 27
#define HALFK 1
#define SENC 258
#define SENC2 (258 * 258)
#define NK_MAX 2700000
#define TAB_BITS 23
#define TAB (1u << TAB_BITS)
#define TMASK (TAB - 1u)
#define ENCMASK 0x7FFFFFFULL           // low 27 bits
#define SCAN_ELEMS 4096                // 256 threads x 16
#define NBLK_SCAN_MAX 1022

#define AUX_TICKET 0
#define AUX_DUP    1
#define AUX_STATE  2

__device__ unsigned long long g_ht[TAB];   // packed (min_idx<<27)|enc; ~0 = empty
__device__ int g_slot[NK_MAX];             // hash slot -> then min flat index
__device__ int g_scan[NK_MAX];             // inclusive scan of winner flags
__device__ int2 g_dup[NK_MAX];             // compacted (dup index i, winner index m)
__device__ unsigned long long g_aux[NBLK_SCAN_MAX + 2];

// 1) per-voxel build: one thread handles all 27 offsets; 3 batches of 9
//    interleaved CAS probe chains for deep MLP.
__global__ __launch_bounds__(256) void k_build(const int* __restrict__ si, int N) {
    int n = blockIdx.x * blockDim.x + threadIdx.x;
    if (n >= N) return;
    int b = __ldg(si + n);
    int x = __ldg(si + N + n);
    int y = __ldg(si + 2 * N + n);
    int z = __ldg(si + 3 * N + n);
    int base = ((b * SENC + x) * SENC + y) * SENC + z;
    int i0 = n * K_VOL;

#pragma unroll
    for (int batch = 0; batch < 3; batch++) {
        unsigned h[9];
        int e[9];
        unsigned long long pk[9];
#pragma unroll
        for (int q = 0; q < 9; q++) {
            int k = batch * 9 + q;
            int off = (k / 9) * SENC2 + ((k / 3) % 3) * SENC + (k % 3);
            e[q] = base + off;
            h[q] = ((unsigned)e[q] * 2654435761u) >> (32 - TAB_BITS);
            pk[q] = ((unsigned long long)(i0 + k) << 27) | (unsigned)e[q];
        }
        unsigned pend = 0x1FFu;
        while (pend) {
            unsigned long long c[9];
#pragma unroll
            for (int q = 0; q < 9; q++)
                if ((pend >> q) & 1u) c[q] = atomicCAS(&g_ht[h[q]], ~0ULL, pk[q]);
#pragma unroll
            for (int q = 0; q < 9; q++) {
                if ((pend >> q) & 1u) {
                    if (c[q] == ~0ULL) pend &= ~(1u << q);
                    else if ((c[q] & ENCMASK) == (unsigned)e[q]) {
                        atomicMin(&g_ht[h[q]], pk[q]);
                        pend &= ~(1u << q);
                    } else h[q] = (h[q] + 1) & TMASK;
                }
            }
        }
#pragma unroll
        for (int q = 0; q < 9; q++) g_slot[i0 + batch * 9 + q] = (int)h[q];
    }
}

// 2) mega-fused: resolve min index, decoupled-lookback scan, km + ok emission,
//    winner feature copy (contiguous dst range per block), dup compaction.
__global__ __launch_bounds__(256) void k_scan(int NK, const int* __restrict__ si, int N,
                                              float* __restrict__ km, float* __restrict__ ok,
                                              const float4* __restrict__ feat,
                                              float4* __restrict__ outf) {
    __shared__ alignas(16) float s_buf[12288];   // 48KB staging
    __shared__ int s_warp[8];
    __shared__ unsigned s_blk;
    __shared__ int s_excl;
    int* s_int = (int*)s_buf;

    int t = threadIdx.x;
    if (t == 0) s_blk = (unsigned)atomicAdd(&g_aux[AUX_TICKET], 1ULL);
    __syncthreads();
    int blk = (int)s_blk;
    int base = blk * SCAN_ELEMS;

    // --- load + resolve min index (coalesced, 16-deep MLP) ---
#pragma unroll
    for (int j = 0; j < 16; j++) {
        int idx = base + j * 256 + t;
        int m = -1;
        if (idx < NK) {
            int s = g_slot[idx];
            m = (int)(g_ht[s] >> 27);
            g_slot[idx] = m;
        }
        s_int[j * 256 + t] = m;
    }
    __syncthreads();

    // --- per-thread serial scan over contiguous 16 ---
    int v[16];
    unsigned fmask = 0;
    int run = 0;
#pragma unroll
    for (int j = 0; j < 16; j++) {
        int l = t * 16 + j;
        int f = (s_int[l] == base + l) ? 1 : 0;
        fmask |= (unsigned)f << j;
        run += f;
        v[j] = run;
    }
    __syncthreads();

    // --- warp + block scan of per-thread sums ---
    int lane = t & 31, wid = t >> 5;
    int inc = run;
#pragma unroll
    for (int off = 1; off < 32; off <<= 1) {
        int y = __shfl_up_sync(0xffffffffu, inc, off);
        if (lane >= off) inc += y;
    }
    if (lane == 31) s_warp[wid] = inc;
    __syncthreads();
    if (t < 8) {
        int w = s_warp[t];
#pragma unroll
        for (int off = 1; off < 8; off <<= 1) {
            int y = __shfl_up_sync(0xffu, w, off);
            if ((int)t >= off) w += y;
        }
        s_warp[t] = w;
    }
    __syncthreads();
    int total = s_warp[7];
    int thr_excl = (inc - run) + (wid ? s_warp[wid - 1] : 0);

    // --- decoupled lookback ---
    if (t == 0) {
        unsigned long long* st = &g_aux[AUX_STATE];
        if (blk == 0) {
            atomicExch(&st[0], (2ULL << 32) | (unsigned)total);
            s_excl = 0;
        } else {
            atomicExch(&st[blk], (1ULL << 32) | (unsigned)total);
            int excl = 0;
            int j = blk - 1;
            for (;;) {
                unsigned long long s;
                do { s = atomicAdd(&st[j], 0ULL); } while ((s >> 32) == 0ULL);
                excl += (int)(unsigned)s;
                if ((s >> 32) == 2ULL) break;
                j--;
            }
            atomicExch(&st[blk], (2ULL << 32) | (unsigned)(excl + total));
            s_excl = excl;
        }
    }
    __syncthreads();
    int bexcl = s_excl;
    int nelem = NK - base; if (nelem > SCAN_ELEMS) nelem = SCAN_ELEMS;

    // --- store inclusive scan (coalesced via shared transpose) ---
#pragma unroll
    for (int j = 0; j < 16; j++) s_int[t * 16 + j] = v[j] + thr_excl + bexcl;
    __syncthreads();
#pragma unroll
    for (int j = 0; j < 16; j++) {
        int idx = base + j * 256 + t;
        if (idx < NK) g_scan[idx] = s_int[j * 256 + t];
    }
    __syncthreads();

    // --- stage km tile (winners; dup rows fixed by k_fin) + collect dups ---
    int dcnt = 0;
    int didx[16];
#pragma unroll
    for (int j = 0; j < 16; j++) {
        int l = t * 16 + j;
        int idx = base + l;
        if (idx < NK) {
            int n = idx / K_VOL;
            int k = idx - n * K_VOL;
            if ((fmask >> j) & 1u) {
                int u = v[j] + thr_excl + bexcl - 1;
                s_buf[3 * l]     = (float)n;
                s_buf[3 * l + 1] = (float)u;
                s_buf[3 * l + 2] = (float)k;
            } else {
                didx[dcnt++] = idx;
            }
        }
    }
    __syncthreads();
    {   // coalesced km write
        float4* dst4 = (float4*)(km + (size_t)3 * base);
        int nf = 3 * nelem;
        int nf4 = nf >> 2;
        for (int q = t; q < nf4; q += 256) dst4[q] = ((float4*)s_buf)[q];
        for (int q = (nf4 << 2) + t; q < nf; q += 256) km[(size_t)3 * base + q] = s_buf[q];
    }
    __syncthreads();

    // --- stage ok tile (winners occupy contiguous u range [bexcl, bexcl+total)) ---
#pragma unroll
    for (int j = 0; j < 16; j++) {
        int l = t * 16 + j;
        int idx = base + l;
        if (idx < NK && ((fmask >> j) & 1u)) {
            int u_loc = v[j] + thr_excl - 1;
            int n = idx / K_VOL;
            int k = idx - n * K_VOL;
            s_buf[3 * u_loc]     = (float)(si[N + n]     + (k / 9)       - HALFK);
            s_buf[3 * u_loc + 1] = (float)(si[2 * N + n] + ((k / 3) % 3) - HALFK);
            s_buf[3 * u_loc + 2] = (float)(si[3 * N + n] + (k % 3)       - HALFK);
        }
    }
    __syncthreads();
    {   // coalesced ok write from row bexcl
        float* dst = ok + (size_t)3 * bexcl;
        int nf = 3 * total;
        for (int q = t; q < nf; q += 256) dst[q] = s_buf[q];
    }
    __syncthreads();

    // --- stage winner source-row map, then 4x-batched coalesced feature copy ---
#pragma unroll
    for (int j = 0; j < 16; j++) {
        int l = t * 16 + j;
        int idx = base + l;
        if (idx < NK && ((fmask >> j) & 1u)) {
            int u_loc = v[j] + thr_excl - 1;
            s_int[u_loc] = idx / K_VOL;
        }
    }
    __syncthreads();
    {
        float4* dst = outf + (size_t)bexcl * 8;
        int lanes = total * 8;
        for (int q = t; q < lanes; q += 1024) {
            float4 vals[4];
#pragma unroll
            for (int r = 0; r < 4; r++) {
                int qq = q + r * 256;
                if (qq < lanes) {
                    int w = qq >> 3, ln = qq & 7;
                    int n = s_int[w];
                    vals[r] = feat[(size_t)n * 8 + ln];
                }
            }
#pragma unroll
            for (int r = 0; r < 4; r++) {
                int qq = q + r * 256;
                if (qq < lanes) dst[qq] = vals[r];
            }
        }
    }

    // --- dup compaction (warp-aggregated append, store (i, m)) ---
    int inc2 = dcnt;
#pragma unroll
    for (int off = 1; off < 32; off <<= 1) {
        int y = __shfl_up_sync(0xffffffffu, inc2, off);
        if (lane >= off) inc2 += y;
    }
    int wtot = __shfl_sync(0xffffffffu, inc2, 31);
    unsigned db = 0;
    if (lane == 31 && wtot > 0) db = (unsigned)atomicAdd(&g_aux[AUX_DUP], (unsigned long long)wtot);
    db = __shfl_sync(0xffffffffu, db, 31);
    int wbase = (int)db + inc2 - dcnt;
    for (int q = 0; q < dcnt; q++) {
        int i = didx[q];
        g_dup[wbase + q] = make_int2(i, g_slot[i]);   // g_slot[i] = m (L2-hot)
    }
}

// 3) fused finale: dup km rows + feature atomicAdds, AND tail fill [U, NK).
__global__ __launch_bounds__(256) void k_fin(int NK, const float* __restrict__ feat,
                                             float* __restrict__ outf, float* __restrict__ km,
                                             float4* __restrict__ outf4, float* __restrict__ ok) {
    long long stride = (long long)gridDim.x * blockDim.x;
    long long tid0 = (long long)blockIdx.x * blockDim.x + threadIdx.x;

    // dups: 4 lanes per dup
    int cnt = (int)g_aux[AUX_DUP];
    long long dlanes = (long long)cnt * 4;
    for (long long q = tid0; q < dlanes; q += stride) {
        int j = (int)(q >> 2);
        int ln = (int)(q & 3);
        int2 im = g_dup[j];
        int i = im.x, m = im.y;
        int u = g_scan[m] - 1;
        int n = i / K_VOL;
        int k = i - n * K_VOL;
        if (ln == 0) {
            km[(size_t)3 * i]     = (float)n;
            km[(size_t)3 * i + 1] = (float)u;
            km[(size_t)3 * i + 2] = (float)k;
        }
        const float4* src = (const float4*)(feat + (size_t)n * 32) + ln * 2;
        float4 a = src[0], b = src[1];
        float* dst = outf + (size_t)u * 32 + ln * 8;
        atomicAdd(dst + 0, a.x); atomicAdd(dst + 1, a.y);
        atomicAdd(dst + 2, a.z); atomicAdd(dst + 3, a.w);
        atomicAdd(dst + 4, b.x); atomicAdd(dst + 5, b.y);
        atomicAdd(dst + 6, b.z); atomicAdd(dst + 7, b.w);
    }

    // tail: 8 lanes per row
    int U = g_scan[NK - 1];
    long long tlanes = (long long)(NK - U) * 8;
    for (long long q = tid0; q < tlanes; q += stride) {
        int r = U + (int)(q >> 3);
        int ln = (int)(q & 7);
        outf4[(size_t)r * 8 + ln] = make_float4(0.f, 0.f, 0.f, 0.f);
        if (ln == 0) {
            ok[(size_t)3 * r]     = -1.0f;
            ok[(size_t)3 * r + 1] = -1.0f;
            ok[(size_t)3 * r + 2] = -1.0f;
        }
    }
}

extern "C" void kernel_launch(void* const* d_in, const int* in_sizes, int n_in,
                              void* d_out, int out_size) {
    const int* si = (const int*)d_in[0];
    const float* feat = (const float*)d_in[1];
    int N = in_sizes[0] / 4;
    int NK = N * K_VOL;

    float* out = (float*)d_out;
    float* out_km = out;
    float* out_ok = out + (size_t)3 * NK;
    float* out_of = out + (size_t)6 * NK;

    static void* p_ht = nullptr, *p_aux = nullptr;
    if (!p_ht) {
        cudaGetSymbolAddress(&p_ht, g_ht);
        cudaGetSymbolAddress(&p_aux, g_aux);
    }

    const int T = 256;
    int nblk = (NK + SCAN_ELEMS - 1) / SCAN_ELEMS;

    cudaMemsetAsync(p_ht, 0xFF, TAB * sizeof(unsigned long long));
    cudaMemsetAsync(p_aux, 0x00, (NBLK_SCAN_MAX + 2) * sizeof(unsigned long long));

    k_build<<<(N + T - 1) / T, T>>>(si, N);
    k_scan<<<nblk, T>>>(NK, si, N, out_km, out_ok, (const float4*)feat, (float4*)out_of);
    k_fin<<<1024, T>>>(NK, feat, out_of, out_km, (float4*)out_of, out_ok);
}

// round 14
// speedup vs baseline: 1.5285x; 1.5285x over previous
#include <cuda_runtime.h>
#include <cstdint>

#define K_VOL 27
#define HALFK 1
#define SENC 258
#define NK_MAX 2700000
#define TAB_BITS 23
#define TAB (1u << TAB_BITS)
#define TMASK (TAB - 1u)
#define ENCMASK 0x7FFFFFFULL           // low 27 bits
#define SCAN_ELEMS 2048                // 256 threads x 8
#define NBLK_SCAN_MAX 1536

#define AUX_TICKET 0
#define AUX_DUP    1
#define AUX_STATE  2

__device__ unsigned long long g_ht[TAB];   // packed (min_idx<<27)|enc; ~0 = empty
__device__ int g_slot[NK_MAX];             // hash slot -> then min flat index
__device__ int g_scan[NK_MAX];             // inclusive scan of winner flags
__device__ int2 g_dup[NK_MAX];             // compacted (dup index i, winner index m)
__device__ unsigned long long g_aux[NBLK_SCAN_MAX + 2];

// 1) encode + hash insert. Direct CAS (no pre-read); 2 entries/thread,
//    interleaved probe chains -> 2 overlapped L2 round trips, high thread count.
__global__ __launch_bounds__(256) void k_build(const int* __restrict__ si, int N, int NK) {
    int p = blockIdx.x * blockDim.x + threadIdx.x;
    int i0 = 2 * p, i1 = 2 * p + 1;
    if (i0 >= NK) return;
    bool has1 = (i1 < NK);

    int n0 = i0 / K_VOL, k0 = i0 - n0 * K_VOL;
    int n1 = has1 ? (i1 / K_VOL) : n0;
    int k1 = has1 ? (i1 - n1 * K_VOL) : k0;

    int b0 = __ldg(si + n0);
    int x0 = __ldg(si + N + n0)     + (k0 / 9);
    int y0 = __ldg(si + 2 * N + n0) + ((k0 / 3) % 3);
    int z0 = __ldg(si + 3 * N + n0) + (k0 % 3);
    int enc0 = ((b0 * SENC + x0) * SENC + y0) * SENC + z0;

    int b1 = __ldg(si + n1);
    int x1 = __ldg(si + N + n1)     + (k1 / 9);
    int y1 = __ldg(si + 2 * N + n1) + ((k1 / 3) % 3);
    int z1 = __ldg(si + 3 * N + n1) + (k1 % 3);
    int enc1 = ((b1 * SENC + x1) * SENC + y1) * SENC + z1;

    unsigned long long pk0 = ((unsigned long long)i0 << 27) | (unsigned)enc0;
    unsigned long long pk1 = ((unsigned long long)i1 << 27) | (unsigned)enc1;
    unsigned h0 = ((unsigned)enc0 * 2654435761u) >> (32 - TAB_BITS);
    unsigned h1 = ((unsigned)enc1 * 2654435761u) >> (32 - TAB_BITS);

    bool d0 = false, d1 = !has1;
    while (!d0 || !d1) {
        unsigned long long c0 = 0, c1 = 0;
        if (!d0) c0 = atomicCAS(&g_ht[h0], ~0ULL, pk0);
        if (!d1) c1 = atomicCAS(&g_ht[h1], ~0ULL, pk1);
        if (!d0) {
            if (c0 == ~0ULL) d0 = true;
            else if ((c0 & ENCMASK) == (unsigned)enc0) { atomicMin(&g_ht[h0], pk0); d0 = true; }
            else h0 = (h0 + 1) & TMASK;
        }
        if (!d1) {
            if (c1 == ~0ULL) d1 = true;
            else if ((c1 & ENCMASK) == (unsigned)enc1) { atomicMin(&g_ht[h1], pk1); d1 = true; }
            else h1 = (h1 + 1) & TMASK;
        }
    }
    if (has1) *(int2*)(g_slot + i0) = make_int2((int)h0, (int)h1);
    else g_slot[i0] = (int)h0;
}

// 2) mega-fused: resolve min index, decoupled-lookback scan, km + ok emission,
//    winner feature copy (contiguous dst range per block), dup compaction.
//    24KB smem -> 8 blocks/SM.
__global__ __launch_bounds__(256) void k_scan(int NK, const int* __restrict__ si, int N,
                                              float* __restrict__ km, float* __restrict__ ok,
                                              const float4* __restrict__ feat,
                                              float4* __restrict__ outf) {
    __shared__ alignas(16) float s_buf[6144];    // 24KB staging
    __shared__ int s_warp[8];
    __shared__ unsigned s_blk;
    __shared__ int s_excl;
    int* s_int = (int*)s_buf;

    int t = threadIdx.x;
    if (t == 0) s_blk = (unsigned)atomicAdd(&g_aux[AUX_TICKET], 1ULL);
    __syncthreads();
    int blk = (int)s_blk;
    int base = blk * SCAN_ELEMS;

    // --- load + resolve min index (coalesced, 8-deep MLP) ---
#pragma unroll
    for (int j = 0; j < 8; j++) {
        int idx = base + j * 256 + t;
        int m = -1;
        if (idx < NK) {
            int s = g_slot[idx];
            m = (int)(g_ht[s] >> 27);
            g_slot[idx] = m;
        }
        s_int[j * 256 + t] = m;
    }
    __syncthreads();

    // --- per-thread serial scan over contiguous 8 ---
    int v[8];
    unsigned fmask = 0;
    int run = 0;
#pragma unroll
    for (int j = 0; j < 8; j++) {
        int l = t * 8 + j;
        int f = (s_int[l] == base + l) ? 1 : 0;
        fmask |= (unsigned)f << j;
        run += f;
        v[j] = run;
    }
    __syncthreads();

    // --- warp + block scan of per-thread sums ---
    int lane = t & 31, wid = t >> 5;
    int inc = run;
#pragma unroll
    for (int off = 1; off < 32; off <<= 1) {
        int y = __shfl_up_sync(0xffffffffu, inc, off);
        if (lane >= off) inc += y;
    }
    if (lane == 31) s_warp[wid] = inc;
    __syncthreads();
    if (t < 8) {
        int w = s_warp[t];
#pragma unroll
        for (int off = 1; off < 8; off <<= 1) {
            int y = __shfl_up_sync(0xffu, w, off);
            if ((int)t >= off) w += y;
        }
        s_warp[t] = w;
    }
    __syncthreads();
    int total = s_warp[7];
    int thr_excl = (inc - run) + (wid ? s_warp[wid - 1] : 0);

    // --- decoupled lookback ---
    if (t == 0) {
        unsigned long long* st = &g_aux[AUX_STATE];
        if (blk == 0) {
            atomicExch(&st[0], (2ULL << 32) | (unsigned)total);
            s_excl = 0;
        } else {
            atomicExch(&st[blk], (1ULL << 32) | (unsigned)total);
            int excl = 0;
            int j = blk - 1;
            for (;;) {
                unsigned long long s;
                do { s = atomicAdd(&st[j], 0ULL); } while ((s >> 32) == 0ULL);
                excl += (int)(unsigned)s;
                if ((s >> 32) == 2ULL) break;
                j--;
            }
            atomicExch(&st[blk], (2ULL << 32) | (unsigned)(excl + total));
            s_excl = excl;
        }
    }
    __syncthreads();
    int bexcl = s_excl;
    int nelem = NK - base; if (nelem > SCAN_ELEMS) nelem = SCAN_ELEMS;

    // --- store inclusive scan (coalesced via shared transpose) ---
#pragma unroll
    for (int j = 0; j < 8; j++) s_int[t * 8 + j] = v[j] + thr_excl + bexcl;
    __syncthreads();
#pragma unroll
    for (int j = 0; j < 8; j++) {
        int idx = base + j * 256 + t;
        if (idx < NK) g_scan[idx] = s_int[j * 256 + t];
    }
    __syncthreads();

    // --- stage km tile (winners; dup rows fixed by k_fin) + collect dups ---
    int dcnt = 0;
    int didx[8];
#pragma unroll
    for (int j = 0; j < 8; j++) {
        int l = t * 8 + j;
        int idx = base + l;
        if (idx < NK) {
            int n = idx / K_VOL;
            int k = idx - n * K_VOL;
            if ((fmask >> j) & 1u) {
                int u = v[j] + thr_excl + bexcl - 1;
                s_buf[3 * l]     = (float)n;
                s_buf[3 * l + 1] = (float)u;
                s_buf[3 * l + 2] = (float)k;
            } else {
                didx[dcnt++] = idx;
            }
        }
    }
    __syncthreads();
    {   // coalesced km write
        float4* dst4 = (float4*)(km + (size_t)3 * base);
        int nf = 3 * nelem;
        int nf4 = nf >> 2;
        for (int q = t; q < nf4; q += 256) dst4[q] = ((float4*)s_buf)[q];
        for (int q = (nf4 << 2) + t; q < nf; q += 256) km[(size_t)3 * base + q] = s_buf[q];
    }
    __syncthreads();

    // --- stage ok tile (winners occupy contiguous u range [bexcl, bexcl+total)) ---
#pragma unroll
    for (int j = 0; j < 8; j++) {
        int l = t * 8 + j;
        int idx = base + l;
        if (idx < NK && ((fmask >> j) & 1u)) {
            int u_loc = v[j] + thr_excl - 1;
            int n = idx / K_VOL;
            int k = idx - n * K_VOL;
            s_buf[3 * u_loc]     = (float)(si[N + n]     + (k / 9)       - HALFK);
            s_buf[3 * u_loc + 1] = (float)(si[2 * N + n] + ((k / 3) % 3) - HALFK);
            s_buf[3 * u_loc + 2] = (float)(si[3 * N + n] + (k % 3)       - HALFK);
        }
    }
    __syncthreads();
    {   // coalesced ok write from row bexcl
        float* dst = ok + (size_t)3 * bexcl;
        int nf = 3 * total;
        for (int q = t; q < nf; q += 256) dst[q] = s_buf[q];
    }
    __syncthreads();

    // --- stage winner source-row map, then 4x-batched coalesced feature copy ---
#pragma unroll
    for (int j = 0; j < 8; j++) {
        int l = t * 8 + j;
        int idx = base + l;
        if (idx < NK && ((fmask >> j) & 1u)) {
            int u_loc = v[j] + thr_excl - 1;
            s_int[u_loc] = idx / K_VOL;
        }
    }
    __syncthreads();
    {
        float4* dst = outf + (size_t)bexcl * 8;
        int lanes = total * 8;
        for (int q = t; q < lanes; q += 1024) {
            float4 vals[4];
#pragma unroll
            for (int r = 0; r < 4; r++) {
                int qq = q + r * 256;
                if (qq < lanes) {
                    int w = qq >> 3, ln = qq & 7;
                    int n = s_int[w];
                    vals[r] = feat[(size_t)n * 8 + ln];
                }
            }
#pragma unroll
            for (int r = 0; r < 4; r++) {
                int qq = q + r * 256;
                if (qq < lanes) dst[qq] = vals[r];
            }
        }
    }

    // --- dup compaction (warp-aggregated append, store (i, m)) ---
    int inc2 = dcnt;
#pragma unroll
    for (int off = 1; off < 32; off <<= 1) {
        int y = __shfl_up_sync(0xffffffffu, inc2, off);
        if (lane >= off) inc2 += y;
    }
    int wtot = __shfl_sync(0xffffffffu, inc2, 31);
    unsigned db = 0;
    if (lane == 31 && wtot > 0) db = (unsigned)atomicAdd(&g_aux[AUX_DUP], (unsigned long long)wtot);
    db = __shfl_sync(0xffffffffu, db, 31);
    int wbase = (int)db + inc2 - dcnt;
    for (int q = 0; q < dcnt; q++) {
        int i = didx[q];
        g_dup[wbase + q] = make_int2(i, g_slot[i]);   // g_slot[i] = m (L2-hot)
    }
}

// 3) fused finale: dup km rows + feature atomicAdds, AND tail fill [U, NK).
__global__ __launch_bounds__(256) void k_fin(int NK, const float* __restrict__ feat,
                                             float* __restrict__ outf, float* __restrict__ km,
                                             float4* __restrict__ outf4, float* __restrict__ ok) {
    long long stride = (long long)gridDim.x * blockDim.x;
    long long tid0 = (long long)blockIdx.x * blockDim.x + threadIdx.x;

    // dups: 4 lanes per dup
    int cnt = (int)g_aux[AUX_DUP];
    long long dlanes = (long long)cnt * 4;
    for (long long q = tid0; q < dlanes; q += stride) {
        int j = (int)(q >> 2);
        int ln = (int)(q & 3);
        int2 im = g_dup[j];
        int i = im.x, m = im.y;
        int u = g_scan[m] - 1;
        int n = i / K_VOL;
        int k = i - n * K_VOL;
        if (ln == 0) {
            km[(size_t)3 * i]     = (float)n;
            km[(size_t)3 * i + 1] = (float)u;
            km[(size_t)3 * i + 2] = (float)k;
        }
        const float4* src = (const float4*)(feat + (size_t)n * 32) + ln * 2;
        float4 a = src[0], b = src[1];
        float* dst = outf + (size_t)u * 32 + ln * 8;
        atomicAdd(dst + 0, a.x); atomicAdd(dst + 1, a.y);
        atomicAdd(dst + 2, a.z); atomicAdd(dst + 3, a.w);
        atomicAdd(dst + 4, b.x); atomicAdd(dst + 5, b.y);
        atomicAdd(dst + 6, b.z); atomicAdd(dst + 7, b.w);
    }

    // tail: 8 lanes per row
    int U = g_scan[NK - 1];
    long long tlanes = (long long)(NK - U) * 8;
    for (long long q = tid0; q < tlanes; q += stride) {
        int r = U + (int)(q >> 3);
        int ln = (int)(q & 7);
        outf4[(size_t)r * 8 + ln] = make_float4(0.f, 0.f, 0.f, 0.f);
        if (ln == 0) {
            ok[(size_t)3 * r]     = -1.0f;
            ok[(size_t)3 * r + 1] = -1.0f;
            ok[(size_t)3 * r + 2] = -1.0f;
        }
    }
}

extern "C" void kernel_launch(void* const* d_in, const int* in_sizes, int n_in,
                              void* d_out, int out_size) {
    const int* si = (const int*)d_in[0];
    const float* feat = (const float*)d_in[1];
    int N = in_sizes[0] / 4;
    int NK = N * K_VOL;

    float* out = (float*)d_out;
    float* out_km = out;
    float* out_ok = out + (size_t)3 * NK;
    float* out_of = out + (size_t)6 * NK;

    static void* p_ht = nullptr, *p_aux = nullptr;
    if (!p_ht) {
        cudaGetSymbolAddress(&p_ht, g_ht);
        cudaGetSymbolAddress(&p_aux, g_aux);
    }

    const int T = 256;
    int nblk = (NK + SCAN_ELEMS - 1) / SCAN_ELEMS;

    cudaMemsetAsync(p_ht, 0xFF, TAB * sizeof(unsigned long long));
    cudaMemsetAsync(p_aux, 0x00, (NBLK_SCAN_MAX + 2) * sizeof(unsigned long long));

    int pairs = (NK + 1) / 2;
    k_build<<<(pairs + T - 1) / T, T>>>(si, N, NK);
    k_scan<<<nblk, T>>>(NK, si, N, out_km, out_ok, (const float4*)feat, (float4*)out_of);
    k_fin<<<1024, T>>>(NK, feat, out_of, out_km, (float4*)out_of, out_ok);
}